// round 1
// baseline (speedup 1.0000x reference)
#include <cuda_runtime.h>
#include <math.h>

#define B_   32
#define S_   200
#define H_   512
#define G4   2048
#define ED_  256
#define NF_  19
#define IN0  275
#define M_   6400
#define PD_  531

// ---------------- scratch (static device memory; no allocation) ----------------
__device__ float g_inp[M_ * IN0];      // LSTM-0 input rows (t*B+b ordering)
__device__ float g_X[M_ * G4];         // precomputed input-gate GEMM (reused L0/L1)
__device__ float g_hall0[M_ * H_];     // layer-0 hidden sequence
__device__ float g_hall1[M_ * H_];     // layer-1 hidden sequence
__device__ float g_hbufA[H_ * B_];     // h ping  (transposed [H][B])
__device__ float g_hbufB[H_ * B_];     // h pong
__device__ float g_cst[H_ * B_];       // c state (transposed [H][B])
__device__ float2 g_partial[800];      // per-block (bce_sum, mask_sum)
__device__ unsigned int g_bar_count = 0;
__device__ volatile unsigned int g_bar_gen = 0;

// ---------------- grid-wide barrier (generation counter, self-resetting) -------
__device__ __forceinline__ void grid_barrier(int nblocks) {
    __syncthreads();
    if (threadIdx.x == 0) {
        unsigned int gen = g_bar_gen;
        __threadfence();
        if (atomicAdd(&g_bar_count, 1u) == (unsigned)(nblocks - 1)) {
            g_bar_count = 0;
            __threadfence();
            g_bar_gen = gen + 1;
        } else {
            while (g_bar_gen == gen) { __nanosleep(64); }
        }
        __threadfence();
    }
    __syncthreads();
}

// ---------------- build LSTM-0 input: [emb | C*c_t], rows ordered t*B+b --------
__global__ void build_inp_kernel(const int* __restrict__ xd,
                                 const float* __restrict__ emb,
                                 const float* __restrict__ Cm,
                                 const float* __restrict__ rep,
                                 const float* __restrict__ seq,
                                 const float* __restrict__ past,
                                 float* __restrict__ inp) {
    int idx = blockIdx.x * 256 + threadIdx.x;
    if (idx >= M_ * IN0) return;
    int row = idx / IN0, d = idx - row * IN0;
    int t = row >> 5, b = row & 31;
    float v;
    if (d < ED_) {
        int x = xd[b * S_ + t];
        v = emb[(size_t)x * ED_ + d];
    } else {
        int f = d - ED_;
        float cv;
        if (f < 7)       cv = rep[(b * (S_ + 1) + t) * 7 + f];
        else if (f < 13) cv = seq[(b * (S_ + 1) + t) * 6 + (f - 7)];
        else             cv = past[(b * (S_ + 1) + t) * 6 + (f - 13)];
        v = Cm[(b * S_ + t) * NF_ + f] * cv;
    }
    inp[idx] = v;
}

// ---------------- transpose init states into [H][B] ----------------------------
__global__ void init_state_kernel(const float* __restrict__ ih,
                                  const float* __restrict__ ic, int layer,
                                  float* __restrict__ hbuf0, float* __restrict__ cst) {
    int idx = blockIdx.x * 256 + threadIdx.x;
    if (idx >= H_ * B_) return;
    int j = idx >> 5, b = idx & 31;
    hbuf0[j * B_ + b] = ih[layer * B_ * H_ + b * H_ + j];
    cst[j * B_ + b]   = ic[layer * B_ * H_ + b * H_ + j];
}

// ---------------- fp32 tiled GEMM:  C = A[M,K] * B[N,K]^T + bias1 + bias2 ------
// 128x128 tile, BK=32, 256 threads, 8x8 microtile.
__global__ void __launch_bounds__(256) gemm_nt_bias(
    const float* __restrict__ A, const float* __restrict__ Bm,
    const float* __restrict__ bias1, const float* __restrict__ bias2,
    float* __restrict__ Cmat, int M, int N, int K) {
    __shared__ float As[32][132];
    __shared__ float Bs[32][132];
    int m0 = blockIdx.y * 128;
    int n0 = blockIdx.x * 128;
    int tid = threadIdx.x;
    int ty = tid >> 4, tx = tid & 15;
    float acc[8][8];
#pragma unroll
    for (int i = 0; i < 8; i++)
#pragma unroll
        for (int j = 0; j < 8; j++) acc[i][j] = 0.f;

    for (int kk = 0; kk < K; kk += 32) {
#pragma unroll
        for (int i = 0; i < 16; i++) {
            int e = tid + i * 256;            // 0..4095
            int m = e >> 5, k = e & 31;
            bool ok = (kk + k) < K;
            As[k][m] = ok ? A[(size_t)(m0 + m) * K + kk + k] : 0.f;
            Bs[k][m] = ok ? Bm[(size_t)(n0 + m) * K + kk + k] : 0.f;
        }
        __syncthreads();
#pragma unroll
        for (int k = 0; k < 32; k++) {
            float a[8], b[8];
            float4 a0 = *(const float4*)&As[k][ty * 8];
            float4 a1 = *(const float4*)&As[k][ty * 8 + 4];
            float4 b0 = *(const float4*)&Bs[k][tx * 8];
            float4 b1 = *(const float4*)&Bs[k][tx * 8 + 4];
            a[0]=a0.x; a[1]=a0.y; a[2]=a0.z; a[3]=a0.w;
            a[4]=a1.x; a[5]=a1.y; a[6]=a1.z; a[7]=a1.w;
            b[0]=b0.x; b[1]=b0.y; b[2]=b0.z; b[3]=b0.w;
            b[4]=b1.x; b[5]=b1.y; b[6]=b1.z; b[7]=b1.w;
#pragma unroll
            for (int i = 0; i < 8; i++)
#pragma unroll
                for (int j = 0; j < 8; j++)
                    acc[i][j] = fmaf(a[i], b[j], acc[i][j]);
        }
        __syncthreads();
    }
#pragma unroll
    for (int i = 0; i < 8; i++) {
        int m = m0 + ty * 8 + i;
#pragma unroll
        for (int j = 0; j < 8; j++) {
            int n = n0 + tx * 8 + j;
            Cmat[(size_t)m * N + n] = acc[i][j] + bias1[n] + bias2[n];
        }
    }
}

// ---------------- persistent LSTM layer scan ------------------------------------
// 128 CTAs x 256 threads, each CTA owns 4 hidden units (16 rows of Whh in smem).
#define NCTA 128
__global__ void __launch_bounds__(256, 1) lstm_layer_kernel(
    const float* __restrict__ X,     // [S*B][4H], row = t*B+b (bias already in)
    const float* __restrict__ Whh,   // [4H][H]
    float* __restrict__ hbuf0,       // [H][B] ping (holds init h)
    float* __restrict__ hbuf1,       // [H][B] pong
    float* __restrict__ cst,         // [H][B] init c
    float* __restrict__ hall)        // [S*B][H] out, row = t*B+b
{
    __shared__ float Ws[16][512];
    __shared__ float gbuf[16][33];
    int tid = threadIdx.x;
    int jb = blockIdx.x * 4;

    for (int idx = tid; idx < 16 * 512; idx += 256) {
        int r = idx >> 9, k = idx & 511;
        int gr = (r >> 2) * H_ + jb + (r & 3);   // gate*(H) + hidden unit
        Ws[r][k] = Whh[(size_t)gr * H_ + k];
    }
    int u = tid >> 5, b = tid & 31;
    float cc = 0.f;
    if (tid < 128) cc = cst[(jb + u) * B_ + b];
    __syncthreads();

    int warp = tid >> 5, lane = tid & 31;
    int r0 = warp * 2, r1 = warp * 2 + 1;

    for (int t = 0; t < S_; t++) {
        const float* hprev = (t & 1) ? hbuf1 : hbuf0;
        float* hnext       = (t & 1) ? hbuf0 : hbuf1;

        // prefetch this step's precomputed input-gate values (overlaps compute)
        float xi = 0.f, xf = 0.f, xg = 0.f, xo = 0.f;
        if (tid < 128) {
            const float* xrow = X + (size_t)(t * B_ + b) * G4 + jb + u;
            xi = xrow[0]; xf = xrow[512]; xg = xrow[1024]; xo = xrow[1536];
        }

        float acc0 = 0.f, acc1 = 0.f;
        const float* hp = hprev + lane;
#pragma unroll 2
        for (int k = 0; k < 512; k += 8) {
            float hv0 = __ldcg(hp + (k + 0) * 32);
            float hv1 = __ldcg(hp + (k + 1) * 32);
            float hv2 = __ldcg(hp + (k + 2) * 32);
            float hv3 = __ldcg(hp + (k + 3) * 32);
            float hv4 = __ldcg(hp + (k + 4) * 32);
            float hv5 = __ldcg(hp + (k + 5) * 32);
            float hv6 = __ldcg(hp + (k + 6) * 32);
            float hv7 = __ldcg(hp + (k + 7) * 32);
            float4 wa0 = *(const float4*)&Ws[r0][k];
            float4 wa1 = *(const float4*)&Ws[r0][k + 4];
            float4 wb0 = *(const float4*)&Ws[r1][k];
            float4 wb1 = *(const float4*)&Ws[r1][k + 4];
            acc0 = fmaf(hv0, wa0.x, acc0); acc0 = fmaf(hv1, wa0.y, acc0);
            acc0 = fmaf(hv2, wa0.z, acc0); acc0 = fmaf(hv3, wa0.w, acc0);
            acc0 = fmaf(hv4, wa1.x, acc0); acc0 = fmaf(hv5, wa1.y, acc0);
            acc0 = fmaf(hv6, wa1.z, acc0); acc0 = fmaf(hv7, wa1.w, acc0);
            acc1 = fmaf(hv0, wb0.x, acc1); acc1 = fmaf(hv1, wb0.y, acc1);
            acc1 = fmaf(hv2, wb0.z, acc1); acc1 = fmaf(hv3, wb0.w, acc1);
            acc1 = fmaf(hv4, wb1.x, acc1); acc1 = fmaf(hv5, wb1.y, acc1);
            acc1 = fmaf(hv6, wb1.z, acc1); acc1 = fmaf(hv7, wb1.w, acc1);
        }
        gbuf[r0][lane] = acc0;
        gbuf[r1][lane] = acc1;
        __syncthreads();

        if (tid < 128) {
            float iv = xi + gbuf[0 + u][b];
            float fv = xf + gbuf[4 + u][b];
            float gv = xg + gbuf[8 + u][b];
            float ov = xo + gbuf[12 + u][b];
            float ig = 1.f / (1.f + expf(-iv));
            float fg = 1.f / (1.f + expf(-fv));
            float og = 1.f / (1.f + expf(-ov));
            cc = fg * cc + ig * tanhf(gv);
            float hv = og * tanhf(cc);
            __stcg(&hnext[(jb + u) * B_ + b], hv);
            hall[(size_t)(t * B_ + b) * H_ + jb + u] = hv;
        }
        grid_barrier(NCTA);
    }
}

// ---------------- gathered prediction + BCE partials ----------------------------
// One warp per row r = b*S+s; pred_1d[r] = dot(pi[r], W_pred[q_t[r]]) + b_pred[q].
__global__ void pred_kernel(const float* __restrict__ hall2,
                            const float* __restrict__ Wp,
                            const float* __restrict__ bp,
                            const int* __restrict__ qt,
                            const float* __restrict__ target,
                            const float* __restrict__ Cm,
                            const float* __restrict__ rep,
                            const float* __restrict__ seq,
                            const float* __restrict__ past,
                            float* __restrict__ out,
                            float2* __restrict__ partial) {
    int warp = threadIdx.x >> 5, lane = threadIdx.x & 31;
    int r = blockIdx.x * 8 + warp;     // 800 blocks * 8 warps = 6400 rows
    int b = r / S_, s = r - b * S_;
    int q = qt[r];
    const float* wrow = Wp + (size_t)q * PD_;
    const float* hrow = hall2 + (size_t)(s * B_ + b) * H_;
    float acc = 0.f;
    for (int d = lane; d < H_; d += 32) acc = fmaf(hrow[d], wrow[d], acc);
    if (lane < NF_) {
        int f = lane, s1 = s + 1;
        float cv;
        if (f < 7)       cv = rep[(b * (S_ + 1) + s1) * 7 + f];
        else if (f < 13) cv = seq[(b * (S_ + 1) + s1) * 6 + (f - 7)];
        else             cv = past[(b * (S_ + 1) + s1) * 6 + (f - 13)];
        float pi = Cm[(b * S_ + s) * NF_ + f] * cv;
        acc = fmaf(pi, wrow[H_ + f], acc);
    }
#pragma unroll
    for (int o = 16; o > 0; o >>= 1) acc += __shfl_xor_sync(0xFFFFFFFFu, acc, o);

    __shared__ float sb[8], sm[8];
    if (lane == 0) {
        float x = acc + bp[q];
        float m = (q > 0) ? 1.f : 0.f;
        float tt = target[r];
        float sg = 1.f / (1.f + expf(-x));
        out[1 + r] = sg * m;
        out[1 + M_ + r] = tt * m;
        float l = fmaxf(x, 0.f) - x * tt + log1pf(expf(-fabsf(x)));
        sb[warp] = l * m;
        sm[warp] = m;
    }
    __syncthreads();
    if (threadIdx.x == 0) {
        float a = 0.f, c = 0.f;
#pragma unroll
        for (int i = 0; i < 8; i++) { a += sb[i]; c += sm[i]; }
        partial[blockIdx.x] = make_float2(a, c);
    }
}

__global__ void finalize_kernel(const float2* __restrict__ partial, int n,
                                float* __restrict__ out) {
    __shared__ float sa[256], sc[256];
    float a = 0.f, c = 0.f;
    for (int i = threadIdx.x; i < n; i += 256) {
        float2 p = partial[i];
        a += p.x; c += p.y;
    }
    sa[threadIdx.x] = a; sc[threadIdx.x] = c;
    __syncthreads();
    for (int s = 128; s > 0; s >>= 1) {
        if (threadIdx.x < s) {
            sa[threadIdx.x] += sa[threadIdx.x + s];
            sc[threadIdx.x] += sc[threadIdx.x + s];
        }
        __syncthreads();
    }
    if (threadIdx.x == 0) out[0] = sa[0] / sc[0];
}

// ---------------- launch --------------------------------------------------------
extern "C" void kernel_launch(void* const* d_in, const int* in_sizes, int n_in,
                              void* d_out, int out_size) {
    const int*   x_data = (const int*)d_in[0];
    const int*   q_t    = (const int*)d_in[1];
    const float* target = (const float*)d_in[2];
    const float* rep    = (const float*)d_in[3];
    const float* past   = (const float*)d_in[4];
    const float* seq    = (const float*)d_in[5];
    const float* embed  = (const float*)d_in[6];
    const float* W_ih0  = (const float*)d_in[7];
    const float* W_hh0  = (const float*)d_in[8];
    const float* b_ih0  = (const float*)d_in[9];
    const float* b_hh0  = (const float*)d_in[10];
    const float* W_ih1  = (const float*)d_in[11];
    const float* W_hh1  = (const float*)d_in[12];
    const float* b_ih1  = (const float*)d_in[13];
    const float* b_hh1  = (const float*)d_in[14];
    const float* W_pred = (const float*)d_in[15];
    const float* b_pred = (const float*)d_in[16];
    const float* Cm     = (const float*)d_in[17];
    const float* init_h = (const float*)d_in[18];
    const float* init_c = (const float*)d_in[19];
    float* out = (float*)d_out;

    float *p_inp, *p_X, *p_hall0, *p_hall1, *p_hA, *p_hB, *p_cst;
    float2* p_part;
    cudaGetSymbolAddress((void**)&p_inp,   g_inp);
    cudaGetSymbolAddress((void**)&p_X,     g_X);
    cudaGetSymbolAddress((void**)&p_hall0, g_hall0);
    cudaGetSymbolAddress((void**)&p_hall1, g_hall1);
    cudaGetSymbolAddress((void**)&p_hA,    g_hbufA);
    cudaGetSymbolAddress((void**)&p_hB,    g_hbufB);
    cudaGetSymbolAddress((void**)&p_cst,   g_cst);
    cudaGetSymbolAddress((void**)&p_part,  g_partial);

    // 1) build LSTM-0 input rows
    build_inp_kernel<<<(M_ * IN0 + 255) / 256, 256>>>(x_data, embed, Cm, rep, seq,
                                                      past, p_inp);
    // 2) X0 = inp @ W_ih0^T + b_ih0 + b_hh0
    gemm_nt_bias<<<dim3(G4 / 128, M_ / 128), 256>>>(p_inp, W_ih0, b_ih0, b_hh0,
                                                    p_X, M_, G4, IN0);
    // 3) layer-0 scan
    init_state_kernel<<<(H_ * B_ + 255) / 256, 256>>>(init_h, init_c, 0, p_hA, p_cst);
    lstm_layer_kernel<<<NCTA, 256>>>(p_X, W_hh0, p_hA, p_hB, p_cst, p_hall0);
    // 4) X1 = h1 @ W_ih1^T + b_ih1 + b_hh1
    gemm_nt_bias<<<dim3(G4 / 128, M_ / 128), 256>>>(p_hall0, W_ih1, b_ih1, b_hh1,
                                                    p_X, M_, G4, H_);
    // 5) layer-1 scan
    init_state_kernel<<<(H_ * B_ + 255) / 256, 256>>>(init_h, init_c, 1, p_hA, p_cst);
    lstm_layer_kernel<<<NCTA, 256>>>(p_X, W_hh1, p_hA, p_hB, p_cst, p_hall1);
    // 6) gathered prediction head + BCE partials
    pred_kernel<<<800, 256>>>(p_hall1, W_pred, b_pred, q_t, target, Cm, rep, seq,
                              past, out, p_part);
    // 7) loss
    finalize_kernel<<<1, 256>>>(p_part, 800, out);
}

// round 2
// speedup vs baseline: 1.6792x; 1.6792x over previous
#include <cuda_runtime.h>
#include <math.h>

#define B_   32
#define S_   200
#define H_   512
#define G4   2048
#define ED_  256
#define NF_  19
#define IN0  275
#define M_   6400
#define PD_  531
#define HP   (H_ + 4)        // padded smem row stride (float) for h

// ---------------- scratch (static device memory; no allocation) ----------------
__device__ float g_inp[M_ * IN0];      // LSTM-0 input rows (t*B+b ordering)
__device__ float g_X[M_ * G4];         // precomputed input-gate GEMM (reused L0/L1)
__device__ float g_hall0[M_ * H_];     // layer-0 hidden sequence
__device__ float g_hall1[M_ * H_];     // layer-1 hidden sequence
__device__ float g_hbufA[B_ * H_];     // h ping   ([B][H])
__device__ float g_hbufB[B_ * H_];     // h pong   ([B][H])
__device__ float g_cst[B_ * H_];       // c init   ([B][H])
__device__ float2 g_partial[800];      // per-block (bce_sum, mask_sum)
__device__ unsigned int g_bar_count = 0;
__device__ volatile unsigned int g_bar_gen = 0;

// ---------------- packed fp32x2 helpers (Blackwell) ----------------------------
__device__ __forceinline__ unsigned long long pk2(float lo, float hi) {
    unsigned long long r;
    asm("mov.b64 %0,{%1,%2};" : "=l"(r) : "f"(lo), "f"(hi));
    return r;
}
__device__ __forceinline__ void ffma2(unsigned long long& d,
                                      unsigned long long a, unsigned long long b) {
    asm("fma.rn.f32x2 %0,%1,%2,%0;" : "+l"(d) : "l"(a), "l"(b));
}
__device__ __forceinline__ float2 up2(unsigned long long v) {
    float2 f;
    asm("mov.b64 {%0,%1},%2;" : "=f"(f.x), "=f"(f.y) : "l"(v));
    return f;
}

// ---------------- grid-wide barrier (generation counter, self-resetting) -------
__device__ __forceinline__ void grid_barrier(int nblocks) {
    __syncthreads();
    if (threadIdx.x == 0) {
        unsigned int gen = g_bar_gen;
        __threadfence();
        if (atomicAdd(&g_bar_count, 1u) == (unsigned)(nblocks - 1)) {
            g_bar_count = 0;
            __threadfence();
            g_bar_gen = gen + 1;
        } else {
            while (g_bar_gen == gen) { __nanosleep(32); }
        }
        __threadfence();
    }
    __syncthreads();
}

// ---------------- build LSTM-0 input: [emb | C*c_t], rows ordered t*B+b --------
__global__ void build_inp_kernel(const int* __restrict__ xd,
                                 const float* __restrict__ emb,
                                 const float* __restrict__ Cm,
                                 const float* __restrict__ rep,
                                 const float* __restrict__ seq,
                                 const float* __restrict__ past,
                                 float* __restrict__ inp) {
    int idx = blockIdx.x * 256 + threadIdx.x;
    if (idx >= M_ * IN0) return;
    int row = idx / IN0, d = idx - row * IN0;
    int t = row >> 5, b = row & 31;
    float v;
    if (d < ED_) {
        int x = xd[b * S_ + t];
        v = emb[(size_t)x * ED_ + d];
    } else {
        int f = d - ED_;
        float cv;
        if (f < 7)       cv = rep[(b * (S_ + 1) + t) * 7 + f];
        else if (f < 13) cv = seq[(b * (S_ + 1) + t) * 6 + (f - 7)];
        else             cv = past[(b * (S_ + 1) + t) * 6 + (f - 13)];
        v = Cm[(b * S_ + t) * NF_ + f] * cv;
    }
    inp[idx] = v;
}

// ---------------- fp32x2 tiled GEMM: C = A[M,K] * B[N,K]^T + bias1 + bias2 -----
// 128x128 tile, BK=32, 256 threads, 8x8 microtile via FFMA2.
__global__ void __launch_bounds__(256) gemm_nt_bias(
    const float* __restrict__ A, const float* __restrict__ Bm,
    const float* __restrict__ bias1, const float* __restrict__ bias2,
    float* __restrict__ Cmat, int M, int N, int K) {
    __shared__ float As[32][132];
    __shared__ float Bs[32][132];
    int m0 = blockIdx.y * 128;
    int n0 = blockIdx.x * 128;
    int tid = threadIdx.x;
    int ty = tid >> 4, tx = tid & 15;
    unsigned long long acc[8][4];
    const unsigned long long Z = 0ull;
#pragma unroll
    for (int i = 0; i < 8; i++)
#pragma unroll
        for (int j = 0; j < 4; j++) acc[i][j] = Z;

    for (int kk = 0; kk < K; kk += 32) {
#pragma unroll
        for (int i = 0; i < 16; i++) {
            int e = tid + i * 256;            // 0..4095
            int m = e >> 5, k = e & 31;
            bool ok = (kk + k) < K;
            As[k][m] = ok ? A[(size_t)(m0 + m) * K + kk + k] : 0.f;
            Bs[k][m] = ok ? Bm[(size_t)(n0 + m) * K + kk + k] : 0.f;
        }
        __syncthreads();
#pragma unroll
        for (int k = 0; k < 32; k++) {
            float4 a0 = *(const float4*)&As[k][ty * 8];
            float4 a1 = *(const float4*)&As[k][ty * 8 + 4];
            ulonglong2 b0 = *(const ulonglong2*)&Bs[k][tx * 8];
            ulonglong2 b1 = *(const ulonglong2*)&Bs[k][tx * 8 + 4];
            unsigned long long aa[8];
            aa[0] = pk2(a0.x, a0.x); aa[1] = pk2(a0.y, a0.y);
            aa[2] = pk2(a0.z, a0.z); aa[3] = pk2(a0.w, a0.w);
            aa[4] = pk2(a1.x, a1.x); aa[5] = pk2(a1.y, a1.y);
            aa[6] = pk2(a1.z, a1.z); aa[7] = pk2(a1.w, a1.w);
#pragma unroll
            for (int i = 0; i < 8; i++) {
                ffma2(acc[i][0], aa[i], b0.x);
                ffma2(acc[i][1], aa[i], b0.y);
                ffma2(acc[i][2], aa[i], b1.x);
                ffma2(acc[i][3], aa[i], b1.y);
            }
        }
        __syncthreads();
    }
#pragma unroll
    for (int i = 0; i < 8; i++) {
        int m = m0 + ty * 8 + i;
#pragma unroll
        for (int j = 0; j < 4; j++) {
            int n = n0 + tx * 8 + j * 2;
            float2 v = up2(acc[i][j]);
            Cmat[(size_t)m * N + n]     = v.x + bias1[n]     + bias2[n];
            Cmat[(size_t)m * N + n + 1] = v.y + bias1[n + 1] + bias2[n + 1];
        }
    }
}

// ---------------- persistent LSTM layer scan ------------------------------------
// 128 CTAs x 256 threads, each CTA owns 4 hidden units (16 gate rows).
// Per step: stage h[B][H] into smem, warps split k 8 ways over all 16 rows,
// FFMA2 dot products, smem partial reduction, gate epilogue on 128 threads.
#define NCTA 128
__global__ void __launch_bounds__(256, 1) lstm_layer_kernel(
    const float* __restrict__ X,     // [S*B][4H], row = t*B+b (bias already in)
    const float* __restrict__ Whh,   // [4H][H]
    float* __restrict__ hbuf0,       // [B][H] ping (holds init h)
    float* __restrict__ hbuf1,       // [B][H] pong
    const float* __restrict__ cst,   // [B][H] init c
    float* __restrict__ hall)        // [S*B][H] out, row = t*B+b
{
    extern __shared__ float smem[];
    float* Ws   = smem;                       // [16][512]   32 KB
    float* hs   = smem + 16 * 512;            // [32][HP]    66 KB
    float* psum = hs + 32 * HP;               // [8][16][32] 16 KB

    int tid = threadIdx.x;
    int jb = blockIdx.x * 4;
    int warp = tid >> 5, lane = tid & 31;

    // load this CTA's 16 W_hh rows (gate-major: r = gate*4 + u)
    for (int idx = tid; idx < 16 * 512; idx += 256) {
        int r = idx >> 9, k = idx & 511;
        int gr = (r >> 2) * H_ + jb + (r & 3);
        Ws[r * 512 + k] = Whh[(size_t)gr * H_ + k];
    }
    int u = tid >> 5, b = tid & 31;           // epilogue mapping (tid<128)
    float cc = 0.f;
    if (tid < 128) cc = cst[b * H_ + jb + u];
    __syncthreads();

    for (int t = 0; t < S_; t++) {
        const float* hprev = (t & 1) ? hbuf1 : hbuf0;
        float* hnext       = (t & 1) ? hbuf0 : hbuf1;

        // prefetch precomputed input-gate values for this step
        float xi = 0.f, xf = 0.f, xg = 0.f, xo = 0.f;
        if (tid < 128) {
            const float* xrow = X + (size_t)(t * B_ + b) * G4 + jb + u;
            xi = xrow[0]; xf = xrow[512]; xg = xrow[1024]; xo = xrow[1536];
        }

        // stage h (64 KB) global [B][H] -> smem [B][HP]
        for (int idx = tid; idx < (H_ / 4) * B_; idx += 256) {
            int bb = idx >> 7, kq = idx & 127;
            float4 v = __ldcg((const float4*)hprev + bb * (H_ / 4) + kq);
            *(float4*)&hs[bb * HP + kq * 4] = v;
        }
        __syncthreads();

        // compute: warp handles k-slice [64*warp, 64*warp+64), all 16 rows
        unsigned long long acc[16];
        const unsigned long long Z = 0ull;
#pragma unroll
        for (int r = 0; r < 16; r++) acc[r] = Z;
        const float* hrow = hs + lane * HP + warp * 64;
#pragma unroll 8
        for (int kb = 0; kb < 16; kb++) {
            ulonglong2 hv = *(const ulonglong2*)&hrow[kb * 4];
            const float* wbase = Ws + warp * 64 + kb * 4;
#pragma unroll
            for (int r = 0; r < 16; r++) {
                ulonglong2 wv = *(const ulonglong2*)&wbase[r * 512];
                ffma2(acc[r], hv.x, wv.x);
                ffma2(acc[r], hv.y, wv.y);
            }
        }
#pragma unroll
        for (int r = 0; r < 16; r++) {
            float2 p = up2(acc[r]);
            psum[(warp * 16 + r) * 32 + lane] = p.x + p.y;
        }
        __syncthreads();

        // epilogue on 128 threads: reduce 8 partials per gate, nonlinearity
        if (tid < 128) {
            float s_i = xi, s_f = xf, s_g = xg, s_o = xo;
#pragma unroll
            for (int w = 0; w < 8; w++) {
                s_i += psum[(w * 16 + 0  + u) * 32 + b];
                s_f += psum[(w * 16 + 4  + u) * 32 + b];
                s_g += psum[(w * 16 + 8  + u) * 32 + b];
                s_o += psum[(w * 16 + 12 + u) * 32 + b];
            }
            float ig = 1.f / (1.f + expf(-s_i));
            float fg = 1.f / (1.f + expf(-s_f));
            float og = 1.f / (1.f + expf(-s_o));
            cc = fg * cc + ig * tanhf(s_g);
            float hv = og * tanhf(cc);
            __stcg(&hnext[b * H_ + jb + u], hv);
            hall[(size_t)(t * B_ + b) * H_ + jb + u] = hv;
        }
        grid_barrier(NCTA);
    }
}

// ---------------- gathered prediction + BCE partials ----------------------------
__global__ void pred_kernel(const float* __restrict__ hall2,
                            const float* __restrict__ Wp,
                            const float* __restrict__ bp,
                            const int* __restrict__ qt,
                            const float* __restrict__ target,
                            const float* __restrict__ Cm,
                            const float* __restrict__ rep,
                            const float* __restrict__ seq,
                            const float* __restrict__ past,
                            float* __restrict__ out,
                            float2* __restrict__ partial) {
    int warp = threadIdx.x >> 5, lane = threadIdx.x & 31;
    int r = blockIdx.x * 8 + warp;     // 800 blocks * 8 warps = 6400 rows
    int b = r / S_, s = r - b * S_;
    int q = qt[r];
    const float* wrow = Wp + (size_t)q * PD_;
    const float* hrow = hall2 + (size_t)(s * B_ + b) * H_;
    float acc = 0.f;
    for (int d = lane; d < H_; d += 32) acc = fmaf(hrow[d], wrow[d], acc);
    if (lane < NF_) {
        int f = lane, s1 = s + 1;
        float cv;
        if (f < 7)       cv = rep[(b * (S_ + 1) + s1) * 7 + f];
        else if (f < 13) cv = seq[(b * (S_ + 1) + s1) * 6 + (f - 7)];
        else             cv = past[(b * (S_ + 1) + s1) * 6 + (f - 13)];
        float pi = Cm[(b * S_ + s) * NF_ + f] * cv;
        acc = fmaf(pi, wrow[H_ + f], acc);
    }
#pragma unroll
    for (int o = 16; o > 0; o >>= 1) acc += __shfl_xor_sync(0xFFFFFFFFu, acc, o);

    __shared__ float sb[8], sm[8];
    if (lane == 0) {
        float x = acc + bp[q];
        float m = (q > 0) ? 1.f : 0.f;
        float tt = target[r];
        float sg = 1.f / (1.f + expf(-x));
        out[1 + r] = sg * m;
        out[1 + M_ + r] = tt * m;
        float l = fmaxf(x, 0.f) - x * tt + log1pf(expf(-fabsf(x)));
        sb[warp] = l * m;
        sm[warp] = m;
    }
    __syncthreads();
    if (threadIdx.x == 0) {
        float a = 0.f, c = 0.f;
#pragma unroll
        for (int i = 0; i < 8; i++) { a += sb[i]; c += sm[i]; }
        partial[blockIdx.x] = make_float2(a, c);
    }
}

__global__ void finalize_kernel(const float2* __restrict__ partial, int n,
                                float* __restrict__ out) {
    __shared__ float sa[256], sc[256];
    float a = 0.f, c = 0.f;
    for (int i = threadIdx.x; i < n; i += 256) {
        float2 p = partial[i];
        a += p.x; c += p.y;
    }
    sa[threadIdx.x] = a; sc[threadIdx.x] = c;
    __syncthreads();
    for (int s = 128; s > 0; s >>= 1) {
        if (threadIdx.x < s) {
            sa[threadIdx.x] += sa[threadIdx.x + s];
            sc[threadIdx.x] += sc[threadIdx.x + s];
        }
        __syncthreads();
    }
    if (threadIdx.x == 0) out[0] = sa[0] / sc[0];
}

// ---------------- launch --------------------------------------------------------
#define LSTM_SMEM ((16 * 512 + 32 * HP + 8 * 16 * 32) * (int)sizeof(float))

extern "C" void kernel_launch(void* const* d_in, const int* in_sizes, int n_in,
                              void* d_out, int out_size) {
    const int*   x_data = (const int*)d_in[0];
    const int*   q_t    = (const int*)d_in[1];
    const float* target = (const float*)d_in[2];
    const float* rep    = (const float*)d_in[3];
    const float* past   = (const float*)d_in[4];
    const float* seq    = (const float*)d_in[5];
    const float* embed  = (const float*)d_in[6];
    const float* W_ih0  = (const float*)d_in[7];
    const float* W_hh0  = (const float*)d_in[8];
    const float* b_ih0  = (const float*)d_in[9];
    const float* b_hh0  = (const float*)d_in[10];
    const float* W_ih1  = (const float*)d_in[11];
    const float* W_hh1  = (const float*)d_in[12];
    const float* b_ih1  = (const float*)d_in[13];
    const float* b_hh1  = (const float*)d_in[14];
    const float* W_pred = (const float*)d_in[15];
    const float* b_pred = (const float*)d_in[16];
    const float* Cm     = (const float*)d_in[17];
    const float* init_h = (const float*)d_in[18];
    const float* init_c = (const float*)d_in[19];
    float* out = (float*)d_out;

    float *p_inp, *p_X, *p_hall0, *p_hall1, *p_hA, *p_hB, *p_cst;
    float2* p_part;
    cudaGetSymbolAddress((void**)&p_inp,   g_inp);
    cudaGetSymbolAddress((void**)&p_X,     g_X);
    cudaGetSymbolAddress((void**)&p_hall0, g_hall0);
    cudaGetSymbolAddress((void**)&p_hall1, g_hall1);
    cudaGetSymbolAddress((void**)&p_hA,    g_hbufA);
    cudaGetSymbolAddress((void**)&p_hB,    g_hbufB);
    cudaGetSymbolAddress((void**)&p_cst,   g_cst);
    cudaGetSymbolAddress((void**)&p_part,  g_partial);

    static int smem_set = 0;
    if (!smem_set) {
        cudaFuncSetAttribute(lstm_layer_kernel,
                             cudaFuncAttributeMaxDynamicSharedMemorySize, LSTM_SMEM);
        smem_set = 1;
    }

    size_t stBytes = (size_t)B_ * H_ * sizeof(float);

    // 1) build LSTM-0 input rows
    build_inp_kernel<<<(M_ * IN0 + 255) / 256, 256>>>(x_data, embed, Cm, rep, seq,
                                                      past, p_inp);
    // 2) X0 = inp @ W_ih0^T + b_ih0 + b_hh0
    gemm_nt_bias<<<dim3(G4 / 128, M_ / 128), 256>>>(p_inp, W_ih0, b_ih0, b_hh0,
                                                    p_X, M_, G4, IN0);
    // 3) layer-0 scan ([B][H] init states are direct copies)
    cudaMemcpyAsync(p_hA, init_h,            stBytes, cudaMemcpyDeviceToDevice, 0);
    cudaMemcpyAsync(p_cst, init_c,           stBytes, cudaMemcpyDeviceToDevice, 0);
    lstm_layer_kernel<<<NCTA, 256, LSTM_SMEM>>>(p_X, W_hh0, p_hA, p_hB, p_cst,
                                                p_hall0);
    // 4) X1 = h1 @ W_ih1^T + b_ih1 + b_hh1
    gemm_nt_bias<<<dim3(G4 / 128, M_ / 128), 256>>>(p_hall0, W_ih1, b_ih1, b_hh1,
                                                    p_X, M_, G4, H_);
    // 5) layer-1 scan
    cudaMemcpyAsync(p_hA, init_h + B_ * H_,  stBytes, cudaMemcpyDeviceToDevice, 0);
    cudaMemcpyAsync(p_cst, init_c + B_ * H_, stBytes, cudaMemcpyDeviceToDevice, 0);
    lstm_layer_kernel<<<NCTA, 256, LSTM_SMEM>>>(p_X, W_hh1, p_hA, p_hB, p_cst,
                                                p_hall1);
    // 6) gathered prediction head + BCE partials
    pred_kernel<<<800, 256>>>(p_hall1, W_pred, b_pred, q_t, target, Cm, rep, seq,
                              past, out, p_part);
    // 7) loss
    finalize_kernel<<<1, 256>>>(p_part, 800, out);
}

// round 4
// speedup vs baseline: 2.1800x; 1.2982x over previous
#include <cuda_runtime.h>
#include <math.h>

#define B_   32
#define S_   200
#define H_   512
#define G4   2048
#define ED_  256
#define NF_  19
#define IN0  275
#define M_   6400
#define PD_  531
#define NCTA 128
#define TW   132                      // smem tile row stride (floats)

// ---------------- scratch (static device memory; no allocation) ----------------
__device__ float g_inpT[IN0 * M_];     // LSTM-0 input, k-major [IN0][M]
__device__ float g_X[M_ * G4];         // input-gate GEMM result (row-major [M][4H])
__device__ float g_hall0T[H_ * M_];    // layer-0 hidden, k-major [H][M]
__device__ float g_hall1T[H_ * M_];    // layer-1 hidden, k-major [H][M]
__device__ float g_WT[512 * G4];       // transposed W_ih (reused L0/L1)
__device__ float g_hbufA[H_ * B_];     // h ping  ([H][B])
__device__ float g_hbufB[H_ * B_];     // h pong  ([H][B])
__device__ float g_cst[H_ * B_];       // c init  ([H][B])
__device__ float2 g_partial[32];       // per-block (bce_sum, mask_sum)
__device__ unsigned int g_bar_count = 0;
__device__ volatile unsigned int g_bar_gen = 0;

// ---------------- packed fp32x2 helpers (Blackwell) ----------------------------
__device__ __forceinline__ unsigned long long pk2(float lo, float hi) {
    unsigned long long r;
    asm("mov.b64 %0,{%1,%2};" : "=l"(r) : "f"(lo), "f"(hi));
    return r;
}
__device__ __forceinline__ void ffma2(unsigned long long& d,
                                      unsigned long long a, unsigned long long b) {
    asm("fma.rn.f32x2 %0,%1,%2,%0;" : "+l"(d) : "l"(a), "l"(b));
}
__device__ __forceinline__ float2 up2(unsigned long long v) {
    float2 f;
    asm("mov.b64 {%0,%1},%2;" : "=f"(f.x), "=f"(f.y) : "l"(v));
    return f;
}
__device__ __forceinline__ void cp16(void* sdst, const void* gsrc) {
    unsigned s = (unsigned)__cvta_generic_to_shared(sdst);
    asm volatile("cp.async.cg.shared.global [%0],[%1],16;" :: "r"(s), "l"(gsrc));
}

// ---------------- grid-wide barrier --------------------------------------------
__device__ __forceinline__ void grid_barrier(int nblocks) {
    __syncthreads();
    if (threadIdx.x == 0) {
        unsigned int gen = g_bar_gen;
        __threadfence();
        if (atomicAdd(&g_bar_count, 1u) == (unsigned)(nblocks - 1)) {
            g_bar_count = 0;
            __threadfence();
            g_bar_gen = gen + 1;
        } else {
            while (g_bar_gen == gen) { __nanosleep(32); }
        }
        __threadfence();
    }
    __syncthreads();
}

// ---------------- build LSTM-0 input (k-major transposed) -----------------------
__global__ void build_inp_kernel(const int* __restrict__ xd,
                                 const float* __restrict__ emb,
                                 const float* __restrict__ Cm,
                                 const float* __restrict__ rep,
                                 const float* __restrict__ seq,
                                 const float* __restrict__ past,
                                 float* __restrict__ inpT) {
    int idx = blockIdx.x * 256 + threadIdx.x;
    if (idx >= M_ * IN0) return;
    int d = idx / M_, col = idx - d * M_;
    int t = col >> 5, b = col & 31;
    float v;
    if (d < ED_) {
        int x = xd[b * S_ + t];
        v = emb[(size_t)x * ED_ + d];
    } else {
        int f = d - ED_;
        float cv;
        if (f < 7)       cv = rep[(b * (S_ + 1) + t) * 7 + f];
        else if (f < 13) cv = seq[(b * (S_ + 1) + t) * 6 + (f - 7)];
        else             cv = past[(b * (S_ + 1) + t) * 6 + (f - 13)];
        v = Cm[(b * S_ + t) * NF_ + f] * cv;
    }
    inpT[idx] = v;
}

// ---------------- generic tiled transpose: out[C][R] = in[R][C]^T ---------------
__global__ void transpose_kernel(const float* __restrict__ in,
                                 float* __restrict__ out, int R, int C) {
    __shared__ float tile[32][33];
    int c0 = blockIdx.x * 32, r0 = blockIdx.y * 32;
    int x = c0 + threadIdx.x;
#pragma unroll
    for (int j = 0; j < 32; j += 8) {
        int y = r0 + threadIdx.y + j;
        if (y < R && x < C) tile[threadIdx.y + j][threadIdx.x] = in[(size_t)y * C + x];
    }
    __syncthreads();
    int x2 = r0 + threadIdx.x;
#pragma unroll
    for (int j = 0; j < 32; j += 8) {
        int y2 = c0 + threadIdx.y + j;
        if (y2 < C && x2 < R) out[(size_t)y2 * R + x2] = tile[threadIdx.x][threadIdx.y + j];
    }
}

// ---------------- init states into [H][B] ---------------------------------------
__global__ void init_state_kernel(const float* __restrict__ ih,
                                  const float* __restrict__ ic, int layer,
                                  float* __restrict__ hbuf0, float* __restrict__ cst) {
    int idx = blockIdx.x * 256 + threadIdx.x;
    if (idx >= H_ * B_) return;
    int j = idx >> 5, b = idx & 31;
    hbuf0[j * B_ + b] = ih[layer * B_ * H_ + b * H_ + j];
    cst[j * B_ + b]   = ic[layer * B_ * H_ + b * H_ + j];
}

// ---------------- GEMM (k-major inputs): C[M][N] = AT^T * BT + bias1 + bias2 ----
// AT: [K][M], BT: [K][N]. 128x128 tile, BK=32, 256 threads, cp.async 2-stage.
__device__ __forceinline__ void gemm_load_stage(
    float* Abuf, float* Bbuf, const float* AT, const float* BT,
    int s, int m0, int n0, int M, int N, int K, int tid) {
    int off = (s & 1) * 32 * TW;
    int kk = s * 32;
#pragma unroll
    for (int i = 0; i < 4; i++) {
        int task = tid + i * 256;
        int row = task >> 5, c = task & 31;
        float* ad = &Abuf[off + row * TW + c * 4];
        float* bd = &Bbuf[off + row * TW + c * 4];
        if (kk + row < K) {
            cp16(ad, AT + (size_t)(kk + row) * M + m0 + c * 4);
            cp16(bd, BT + (size_t)(kk + row) * N + n0 + c * 4);
        } else {
            *(float4*)ad = make_float4(0.f, 0.f, 0.f, 0.f);
            *(float4*)bd = make_float4(0.f, 0.f, 0.f, 0.f);
        }
    }
    asm volatile("cp.async.commit_group;" ::);
}

__global__ void __launch_bounds__(256) gemm_tt_bias(
    const float* __restrict__ AT, const float* __restrict__ BT,
    const float* __restrict__ bias1, const float* __restrict__ bias2,
    float* __restrict__ Cmat, int M, int N, int K) {
    extern __shared__ float sm[];
    float* Abuf = sm;
    float* Bbuf = sm + 2 * 32 * TW;
    int m0 = blockIdx.y * 128, n0 = blockIdx.x * 128;
    int tid = threadIdx.x;
    int ty = tid >> 4, tx = tid & 15;
    int nk = (K + 31) / 32;

    unsigned long long acc[8][4];
#pragma unroll
    for (int i = 0; i < 8; i++)
#pragma unroll
        for (int j = 0; j < 4; j++) acc[i][j] = 0ull;

    gemm_load_stage(Abuf, Bbuf, AT, BT, 0, m0, n0, M, N, K, tid);

    for (int s = 0; s < nk; s++) {
        if (s + 1 < nk) {
            gemm_load_stage(Abuf, Bbuf, AT, BT, s + 1, m0, n0, M, N, K, tid);
            asm volatile("cp.async.wait_group 1;" ::);
        } else {
            asm volatile("cp.async.wait_group 0;" ::);
        }
        __syncthreads();
        const float* As = Abuf + (s & 1) * 32 * TW;
        const float* Bs = Bbuf + (s & 1) * 32 * TW;
#pragma unroll 8
        for (int k = 0; k < 32; k++) {
            float4 a0 = *(const float4*)&As[k * TW + ty * 8];
            float4 a1 = *(const float4*)&As[k * TW + ty * 8 + 4];
            ulonglong2 b0 = *(const ulonglong2*)&Bs[k * TW + tx * 8];
            ulonglong2 b1 = *(const ulonglong2*)&Bs[k * TW + tx * 8 + 4];
            unsigned long long aa[8];
            aa[0] = pk2(a0.x, a0.x); aa[1] = pk2(a0.y, a0.y);
            aa[2] = pk2(a0.z, a0.z); aa[3] = pk2(a0.w, a0.w);
            aa[4] = pk2(a1.x, a1.x); aa[5] = pk2(a1.y, a1.y);
            aa[6] = pk2(a1.z, a1.z); aa[7] = pk2(a1.w, a1.w);
#pragma unroll
            for (int i = 0; i < 8; i++) {
                ffma2(acc[i][0], aa[i], b0.x);
                ffma2(acc[i][1], aa[i], b0.y);
                ffma2(acc[i][2], aa[i], b1.x);
                ffma2(acc[i][3], aa[i], b1.y);
            }
        }
        __syncthreads();
    }
#pragma unroll
    for (int i = 0; i < 8; i++) {
        int m = m0 + ty * 8 + i;
#pragma unroll
        for (int j = 0; j < 4; j++) {
            int n = n0 + tx * 8 + j * 2;
            float2 v = up2(acc[i][j]);
            Cmat[(size_t)m * N + n]     = v.x + bias1[n]     + bias2[n];
            Cmat[(size_t)m * N + n + 1] = v.y + bias1[n + 1] + bias2[n + 1];
        }
    }
}
#define GSMEM (4 * 32 * TW * (int)sizeof(float))

// ---------------- persistent LSTM layer scan ------------------------------------
// 128 CTAs x 256 threads; CTA owns 4 hidden units (16 gate rows in smem).
// h kept in [H][B] so each warp streams its k-slice straight from L2 (no staging).
__global__ void __launch_bounds__(256, 1) lstm_layer_kernel(
    const float* __restrict__ X,     // [S*B][4H], row = t*B+b (bias folded in)
    const float* __restrict__ Whh,   // [4H][H]
    float* __restrict__ hbuf0,       // [H][B] ping (init h)
    float* __restrict__ hbuf1,       // [H][B] pong
    const float* __restrict__ cst,   // [H][B] init c
    float* __restrict__ hallT)       // [H][S*B] out (k-major)
{
    extern __shared__ float smem[];
    float* Ws   = smem;               // [16][512] 32 KB
    float* psum = smem + 16 * 512;    // [8][16][32] 16 KB

    int tid = threadIdx.x;
    int jb = blockIdx.x * 4;
    int warp = tid >> 5, lane = tid & 31;

    for (int idx = tid; idx < 16 * 512; idx += 256) {
        int r = idx >> 9, k = idx & 511;
        int gr = (r >> 2) * H_ + jb + (r & 3);
        Ws[r * 512 + k] = Whh[(size_t)gr * H_ + k];
    }
    int u = warp, b = lane;
    float cc = 0.f;
    if (tid < 128) cc = cst[(jb + u) * B_ + b];
    __syncthreads();

    const int k0 = warp * 64;
    for (int t = 0; t < S_; t++) {
        const float* hprev = (t & 1) ? hbuf1 : hbuf0;
        float* hnext       = (t & 1) ? hbuf0 : hbuf1;

        float xi = 0.f, xf = 0.f, xg = 0.f, xo = 0.f;
        if (tid < 128) {
            const float* xrow = X + (size_t)(t * B_ + b) * G4 + jb + u;
            xi = xrow[0]; xf = xrow[512]; xg = xrow[1024]; xo = xrow[1536];
        }

        unsigned long long acc[16];
#pragma unroll
        for (int r = 0; r < 16; r++) acc[r] = 0ull;
        const float* hp = hprev + k0 * B_ + lane;
#pragma unroll
        for (int kb = 0; kb < 8; kb++) {
            float h0 = __ldcg(hp + (kb * 8 + 0) * B_);
            float h1 = __ldcg(hp + (kb * 8 + 1) * B_);
            float h2 = __ldcg(hp + (kb * 8 + 2) * B_);
            float h3 = __ldcg(hp + (kb * 8 + 3) * B_);
            float h4 = __ldcg(hp + (kb * 8 + 4) * B_);
            float h5 = __ldcg(hp + (kb * 8 + 5) * B_);
            float h6 = __ldcg(hp + (kb * 8 + 6) * B_);
            float h7 = __ldcg(hp + (kb * 8 + 7) * B_);
            unsigned long long hv0 = pk2(h0, h1), hv1 = pk2(h2, h3);
            unsigned long long hv2 = pk2(h4, h5), hv3 = pk2(h6, h7);
            const float* wb = Ws + k0 + kb * 8;
#pragma unroll
            for (int r = 0; r < 16; r++) {
                ulonglong2 w0 = *(const ulonglong2*)(wb + r * 512);
                ulonglong2 w1 = *(const ulonglong2*)(wb + r * 512 + 4);
                ffma2(acc[r], hv0, w0.x);
                ffma2(acc[r], hv1, w0.y);
                ffma2(acc[r], hv2, w1.x);
                ffma2(acc[r], hv3, w1.y);
            }
        }
#pragma unroll
        for (int r = 0; r < 16; r++) {
            float2 p = up2(acc[r]);
            psum[(warp * 16 + r) * 32 + lane] = p.x + p.y;
        }
        __syncthreads();

        if (tid < 128) {
            float s_i = xi, s_f = xf, s_g = xg, s_o = xo;
#pragma unroll
            for (int w = 0; w < 8; w++) {
                s_i += psum[(w * 16 + 0  + u) * 32 + b];
                s_f += psum[(w * 16 + 4  + u) * 32 + b];
                s_g += psum[(w * 16 + 8  + u) * 32 + b];
                s_o += psum[(w * 16 + 12 + u) * 32 + b];
            }
            float ig = 1.f / (1.f + expf(-s_i));
            float fg = 1.f / (1.f + expf(-s_f));
            float og = 1.f / (1.f + expf(-s_o));
            cc = fg * cc + ig * tanhf(s_g);
            float hv = og * tanhf(cc);
            __stcg(&hnext[(jb + u) * B_ + b], hv);
            hallT[(size_t)(jb + u) * M_ + t * B_ + b] = hv;
        }
        grid_barrier(NCTA);
    }
}
#define LSMEM ((16 * 512 + 8 * 16 * 32) * (int)sizeof(float))

// ---------------- gathered prediction + BCE partials ----------------------------
// Thread-per-column; hallT reads coalesced across the warp.
__global__ void pred_kernel(const float* __restrict__ hallT,
                            const float* __restrict__ Wp,
                            const float* __restrict__ bp,
                            const int* __restrict__ qt,
                            const float* __restrict__ target,
                            const float* __restrict__ Cm,
                            const float* __restrict__ rep,
                            const float* __restrict__ seq,
                            const float* __restrict__ past,
                            float* __restrict__ out,
                            float2* __restrict__ partial) {
    int col = blockIdx.x * 256 + threadIdx.x;     // t*B+b ordering
    int b = col & 31, s = col >> 5;
    int r = b * S_ + s;
    int q = qt[r];
    const float* wrow = Wp + (size_t)q * PD_;
    const float* hc = hallT + col;
    float acc = bp[q];
#pragma unroll 8
    for (int d = 0; d < H_; d++) acc = fmaf(hc[(size_t)d * M_], wrow[d], acc);
#pragma unroll
    for (int f = 0; f < NF_; f++) {
        float cv;
        if (f < 7)       cv = rep[(b * (S_ + 1) + s + 1) * 7 + f];
        else if (f < 13) cv = seq[(b * (S_ + 1) + s + 1) * 6 + (f - 7)];
        else             cv = past[(b * (S_ + 1) + s + 1) * 6 + (f - 13)];
        float pi = Cm[(b * S_ + s) * NF_ + f] * cv;
        acc = fmaf(pi, wrow[H_ + f], acc);
    }
    float m = (q > 0) ? 1.f : 0.f;
    float tt = target[r];
    float sg = 1.f / (1.f + expf(-acc));
    out[1 + r] = sg * m;
    out[1 + M_ + r] = tt * m;
    float l = fmaxf(acc, 0.f) - acc * tt + log1pf(expf(-fabsf(acc)));

    __shared__ float sb[256], sm2[256];
    sb[threadIdx.x] = l * m;
    sm2[threadIdx.x] = m;
    __syncthreads();
    for (int st = 128; st > 0; st >>= 1) {
        if (threadIdx.x < st) {
            sb[threadIdx.x] += sb[threadIdx.x + st];
            sm2[threadIdx.x] += sm2[threadIdx.x + st];
        }
        __syncthreads();
    }
    if (threadIdx.x == 0) partial[blockIdx.x] = make_float2(sb[0], sm2[0]);
}

__global__ void finalize_kernel(const float2* __restrict__ partial, int n,
                                float* __restrict__ out) {
    __shared__ float sa[32], sc[32];
    float a = 0.f, c = 0.f;
    if (threadIdx.x < n) { float2 p = partial[threadIdx.x]; a = p.x; c = p.y; }
    sa[threadIdx.x] = a; sc[threadIdx.x] = c;
    __syncthreads();
    for (int s = 16; s > 0; s >>= 1) {
        if (threadIdx.x < s) {
            sa[threadIdx.x] += sa[threadIdx.x + s];
            sc[threadIdx.x] += sc[threadIdx.x + s];
        }
        __syncthreads();
    }
    if (threadIdx.x == 0) out[0] = sa[0] / sc[0];
}

// ---------------- launch --------------------------------------------------------
extern "C" void kernel_launch(void* const* d_in, const int* in_sizes, int n_in,
                              void* d_out, int out_size) {
    const int*   x_data = (const int*)d_in[0];
    const int*   q_t    = (const int*)d_in[1];
    const float* target = (const float*)d_in[2];
    const float* rep    = (const float*)d_in[3];
    const float* past   = (const float*)d_in[4];
    const float* seq    = (const float*)d_in[5];
    const float* embed  = (const float*)d_in[6];
    const float* W_ih0  = (const float*)d_in[7];
    const float* W_hh0  = (const float*)d_in[8];
    const float* b_ih0  = (const float*)d_in[9];
    const float* b_hh0  = (const float*)d_in[10];
    const float* W_ih1  = (const float*)d_in[11];
    const float* W_hh1  = (const float*)d_in[12];
    const float* b_ih1  = (const float*)d_in[13];
    const float* b_hh1  = (const float*)d_in[14];
    const float* W_pred = (const float*)d_in[15];
    const float* b_pred = (const float*)d_in[16];
    const float* Cm     = (const float*)d_in[17];
    const float* init_h = (const float*)d_in[18];
    const float* init_c = (const float*)d_in[19];
    float* out = (float*)d_out;

    float *p_inpT, *p_X, *p_h0T, *p_h1T, *p_WT, *p_hA, *p_hB, *p_cst;
    float2* p_part;
    cudaGetSymbolAddress((void**)&p_inpT, g_inpT);
    cudaGetSymbolAddress((void**)&p_X,    g_X);
    cudaGetSymbolAddress((void**)&p_h0T,  g_hall0T);
    cudaGetSymbolAddress((void**)&p_h1T,  g_hall1T);
    cudaGetSymbolAddress((void**)&p_WT,   g_WT);
    cudaGetSymbolAddress((void**)&p_hA,   g_hbufA);
    cudaGetSymbolAddress((void**)&p_hB,   g_hbufB);
    cudaGetSymbolAddress((void**)&p_cst,  g_cst);
    cudaGetSymbolAddress((void**)&p_part, g_partial);

    // deterministic every call (no static guards; not stream-ordered, capture-safe)
    cudaFuncSetAttribute(gemm_tt_bias,
                         cudaFuncAttributeMaxDynamicSharedMemorySize, GSMEM);
    cudaFuncSetAttribute(lstm_layer_kernel,
                         cudaFuncAttributeMaxDynamicSharedMemorySize, LSMEM);

    // 1) build LSTM-0 input rows (k-major)
    build_inp_kernel<<<(M_ * IN0 + 255) / 256, 256>>>(x_data, embed, Cm, rep, seq,
                                                      past, p_inpT);
    // 2) X0 = inp @ W_ih0^T + b_ih0 + b_hh0   (both operands k-major)
    transpose_kernel<<<dim3((IN0 + 31) / 32, G4 / 32), dim3(32, 8)>>>(W_ih0, p_WT,
                                                                      G4, IN0);
    gemm_tt_bias<<<dim3(G4 / 128, M_ / 128), 256, GSMEM>>>(p_inpT, p_WT, b_ih0,
                                                           b_hh0, p_X, M_, G4, IN0);
    // 3) layer-0 scan
    init_state_kernel<<<(H_ * B_ + 255) / 256, 256>>>(init_h, init_c, 0, p_hA, p_cst);
    lstm_layer_kernel<<<NCTA, 256, LSMEM>>>(p_X, W_hh0, p_hA, p_hB, p_cst, p_h0T);
    // 4) X1 = h1 @ W_ih1^T + b_ih1 + b_hh1
    transpose_kernel<<<dim3(H_ / 32, G4 / 32), dim3(32, 8)>>>(W_ih1, p_WT, G4, H_);
    gemm_tt_bias<<<dim3(G4 / 128, M_ / 128), 256, GSMEM>>>(p_h0T, p_WT, b_ih1,
                                                           b_hh1, p_X, M_, G4, H_);
    // 5) layer-1 scan
    init_state_kernel<<<(H_ * B_ + 255) / 256, 256>>>(init_h, init_c, 1, p_hA, p_cst);
    lstm_layer_kernel<<<NCTA, 256, LSMEM>>>(p_X, W_hh1, p_hA, p_hB, p_cst, p_h1T);
    // 6) gathered prediction head + BCE partials
    pred_kernel<<<M_ / 256, 256>>>(p_h1T, W_pred, b_pred, q_t, target, Cm, rep,
                                   seq, past, out, p_part);
    // 7) loss
    finalize_kernel<<<1, 32>>>(p_part, M_ / 256, out);
}